// round 3
// baseline (speedup 1.0000x reference)
#include <cuda_runtime.h>
#include <math.h>

#define NN 100000
#define EE 1600000
#define F_IN 256
#define DIM  32
#define NC   40
#define SCAN_B 1024

// ---------------- scratch (device globals; no allocation allowed) ----------
__device__ __align__(256) float g_y[NN * DIM];   // x @ W1l
__device__ __align__(256) float g_r[NN * DIM];   // x @ W1r
__device__ __align__(256) float g_h[NN * DIM];   // layer-1 output
__device__ __align__(256) float g_invdeg[NN];
__device__ __align__(256) int   g_degi[NN];
__device__ __align__(256) int   g_rowptr[NN];
__device__ __align__(256) int   g_cur[NN];
__device__ __align__(256) int   g_csr[EE];
__device__ __align__(256) int   g_blksum[128];
__device__ int g_shift;   // 1 if edge_index is int64, 0 if int32

// ---------------- edge access helpers ---------------------------------------
// Read edge endpoint: words = edge buffer viewed as 32-bit.
// int32: value at word [which*E + e]. int64 (LE, vals < 2^31): low word at
// [(which*E + e) * 2]. Unified: word[(which*E + e) << g_shift].
__device__ __forceinline__ int edge_get(const int* __restrict__ w, int E,
                                        int which, int e, int shift, int N) {
    int v = w[(size_t)((size_t)which * E + e) << shift];
    return min(max(v, 0), N - 1);
}

// Detect dtype: odd words all-zero over first 2048 words => int64.
__global__ void __launch_bounds__(1024) k_detect(const int* __restrict__ w) {
    __shared__ int any_nz;
    if (threadIdx.x == 0) any_nz = 0;
    __syncthreads();
    if (w[2 * threadIdx.x + 1] != 0) atomicOr(&any_nz, 1);
    __syncthreads();
    if (threadIdx.x == 0) g_shift = any_nz ? 0 : 1;
}

// ---------------- packed f32x2 helpers --------------------------------------
__device__ __forceinline__ unsigned long long pack2(float a, float b) {
    unsigned long long d;
    asm("mov.b64 %0, {%1,%2};" : "=l"(d) : "f"(a), "f"(b));
    return d;
}
__device__ __forceinline__ unsigned long long bcast2(float v) {
    unsigned long long d;
    asm("mov.b64 %0, {%1,%1};" : "=l"(d) : "f"(v));
    return d;
}
__device__ __forceinline__ void fma2(unsigned long long& d,
                                     unsigned long long a,
                                     unsigned long long b) {
    asm("fma.rn.f32x2 %0, %1, %2, %0;" : "+l"(d) : "l"(a), "l"(b));
}
__device__ __forceinline__ float f4c(const float4& v, int j) {
    return j == 0 ? v.x : j == 1 ? v.y : j == 2 ? v.z : v.w;
}

// ---------------- CSR build --------------------------------------------------
__global__ void k_zero(int N) {
    int i = blockIdx.x * blockDim.x + threadIdx.x;
    if (i < N) g_degi[i] = 0;
}

__global__ void k_deg(const int* __restrict__ w, int E, int N) {
    int i = blockIdx.x * blockDim.x + threadIdx.x;
    if (i >= E) return;
    int d = edge_get(w, E, 1, i, g_shift, N);
    atomicAdd(&g_degi[d], 1);
}

__global__ void __launch_bounds__(SCAN_B) k_scanA(int N) {
    __shared__ int sm[SCAN_B];
    int t = threadIdx.x;
    int i = blockIdx.x * SCAN_B + t;
    int v = (i < N) ? g_degi[i] : 0;
    sm[t] = v;
    __syncthreads();
    #pragma unroll
    for (int o = 1; o < SCAN_B; o <<= 1) {
        int add = (t >= o) ? sm[t - o] : 0;
        __syncthreads();
        sm[t] += add;
        __syncthreads();
    }
    if (i < N) g_rowptr[i] = sm[t] - v;
    if (t == SCAN_B - 1) g_blksum[blockIdx.x] = sm[t];
}

__global__ void __launch_bounds__(128) k_scanB(int nb) {
    __shared__ int sm[128];
    int t = threadIdx.x;
    int v = (t < nb) ? g_blksum[t] : 0;
    sm[t] = v;
    __syncthreads();
    #pragma unroll
    for (int o = 1; o < 128; o <<= 1) {
        int add = (t >= o) ? sm[t - o] : 0;
        __syncthreads();
        sm[t] += add;
        __syncthreads();
    }
    if (t < nb) g_blksum[t] = sm[t] - v;
}

__global__ void k_scanC(int N) {
    int i = blockIdx.x * blockDim.x + threadIdx.x;
    if (i >= N) return;
    int rp = g_rowptr[i] + g_blksum[i >> 10];
    g_rowptr[i] = rp;
    g_cur[i] = rp;
    g_invdeg[i] = 1.0f / fmaxf((float)g_degi[i], 1.0f);
}

__global__ void k_fill(const int* __restrict__ w, int E, int N) {
    int e = blockIdx.x * blockDim.x + threadIdx.x;
    if (e >= E) return;
    int shift = g_shift;
    int s = edge_get(w, E, 0, e, shift, N);
    int d = edge_get(w, E, 1, e, shift, N);
    int pos = atomicAdd(&g_cur[d], 1);
    g_csr[min(pos, EE - 1)] = s;
}

// ---------------- GEMM1: y = x@W1l, r = x@W1r (FFMA2) ------------------------
__global__ void __launch_bounds__(512) k_gemm1(const float* __restrict__ x,
                                               const float* __restrict__ W1l,
                                               const float* __restrict__ W1r,
                                               int N) {
    __shared__ float2 sW[128 * DIM];   // 32 KB: half of K at a time
    const int warp = threadIdx.x >> 5;
    const int lane = threadIdx.x & 31;
    const int row0 = blockIdx.x * 64 + warp * 4;

    const int r0 = min(row0 + 0, N - 1);
    const int r1 = min(row0 + 1, N - 1);
    const int r2 = min(row0 + 2, N - 1);
    const int r3 = min(row0 + 3, N - 1);

    unsigned long long a0 = 0ull, a1 = 0ull, a2 = 0ull, a3 = 0ull;

    for (int half = 0; half < 2; ++half) {
        const int kbase = half * 128;
        if (half) __syncthreads();
        for (int i = threadIdx.x; i < 128 * DIM; i += 512) {
            int k = i >> 5, c = i & 31;
            sW[i] = make_float2(W1l[(kbase + k) * DIM + c],
                                W1r[(kbase + k) * DIM + c]);
        }
        __syncthreads();

        const float4* x0 = (const float4*)(x + (size_t)r0 * F_IN + kbase);
        const float4* x1 = (const float4*)(x + (size_t)r1 * F_IN + kbase);
        const float4* x2 = (const float4*)(x + (size_t)r2 * F_IN + kbase);
        const float4* x3 = (const float4*)(x + (size_t)r3 * F_IN + kbase);

        #pragma unroll 4
        for (int k4 = 0; k4 < 32; ++k4) {
            float4 v0 = x0[k4], v1 = x1[k4], v2 = x2[k4], v3 = x3[k4];
            #pragma unroll
            for (int j = 0; j < 4; ++j) {
                float2 w = sW[(k4 * 4 + j) * DIM + lane];
                unsigned long long wp = pack2(w.x, w.y);
                fma2(a0, bcast2(f4c(v0, j)), wp);
                fma2(a1, bcast2(f4c(v1, j)), wp);
                fma2(a2, bcast2(f4c(v2, j)), wp);
                fma2(a3, bcast2(f4c(v3, j)), wp);
            }
        }
    }

    float lo, hi;
    if (row0 + 0 < N) {
        asm("mov.b64 {%0,%1}, %2;" : "=f"(lo), "=f"(hi) : "l"(a0));
        g_y[r0 * DIM + lane] = lo; g_r[r0 * DIM + lane] = hi;
    }
    if (row0 + 1 < N) {
        asm("mov.b64 {%0,%1}, %2;" : "=f"(lo), "=f"(hi) : "l"(a1));
        g_y[r1 * DIM + lane] = lo; g_r[r1 * DIM + lane] = hi;
    }
    if (row0 + 2 < N) {
        asm("mov.b64 {%0,%1}, %2;" : "=f"(lo), "=f"(hi) : "l"(a2));
        g_y[r2 * DIM + lane] = lo; g_r[r2 * DIM + lane] = hi;
    }
    if (row0 + 3 < N) {
        asm("mov.b64 {%0,%1}, %2;" : "=f"(lo), "=f"(hi) : "l"(a3));
        g_y[r3 * DIM + lane] = lo; g_r[r3 * DIM + lane] = hi;
    }
}

// ---------------- layer 1: gather(y) -> h = relu(agg*invd + r + b1) ----------
__global__ void __launch_bounds__(256) k_l1(const float* __restrict__ b1, int N) {
    int warp = threadIdx.x >> 5;
    int lane = threadIdx.x & 31;
    int n = blockIdx.x * 8 + warp;
    if (n >= N) return;

    int start = g_rowptr[n];
    int dn    = g_degi[n];
    float acc = 0.f;
    for (int j0 = 0; j0 < dn; j0 += 32) {
        int idx = (j0 + lane < dn) ? g_csr[start + j0 + lane] : 0;
        int cnt = min(32, dn - j0);
        for (int k = 0; k < cnt; ++k) {
            int s = __shfl_sync(0xffffffffu, idx, k);
            acc += g_y[(size_t)s * DIM + lane];
        }
    }
    float v = acc * g_invdeg[n] + g_r[(size_t)n * DIM + lane] + b1[lane];
    g_h[(size_t)n * DIM + lane] = fmaxf(v, 0.f);
}

// ---------------- layer 2 + log_softmax (gathers h in-register) --------------
__global__ void __launch_bounds__(256) k_out(const float* __restrict__ W2l,
                                             const float* __restrict__ W2r,
                                             const float* __restrict__ b2,
                                             float* __restrict__ out, int N) {
    __shared__ float sWl[DIM * 64];
    __shared__ float sWr[DIM * 64];
    for (int i = threadIdx.x; i < DIM * 64; i += 256) {
        int k = i >> 6, c = i & 63;
        sWl[i] = (c < NC) ? W2l[k * NC + c] : 0.f;
        sWr[i] = (c < NC) ? W2r[k * NC + c] : 0.f;
    }
    __syncthreads();

    int warp = threadIdx.x >> 5;
    int lane = threadIdx.x & 31;
    int n = blockIdx.x * 8 + warp;
    if (n >= N) return;

    int start = g_rowptr[n];
    int dn    = g_degi[n];
    float acc = 0.f;
    for (int j0 = 0; j0 < dn; j0 += 32) {
        int idx = (j0 + lane < dn) ? g_csr[start + j0 + lane] : 0;
        int cnt = min(32, dn - j0);
        for (int k = 0; k < cnt; ++k) {
            int s = __shfl_sync(0xffffffffu, idx, k);
            acc += g_h[(size_t)s * DIM + lane];
        }
    }
    float a_l = acc * g_invdeg[n];
    float h_l = g_h[(size_t)n * DIM + lane];

    float acc0 = b2[lane];
    float acc1 = (lane < NC - 32) ? b2[32 + lane] : 0.f;

    #pragma unroll
    for (int k = 0; k < DIM; ++k) {
        float hk = __shfl_sync(0xffffffffu, h_l, k);
        float ak = __shfl_sync(0xffffffffu, a_l, k);
        acc0 = fmaf(ak, sWl[k * 64 + lane],      acc0);
        acc0 = fmaf(hk, sWr[k * 64 + lane],      acc0);
        acc1 = fmaf(ak, sWl[k * 64 + 32 + lane], acc1);
        acc1 = fmaf(hk, sWr[k * 64 + 32 + lane], acc1);
    }

    bool has1 = (lane < NC - 32);
    float v1 = has1 ? acc1 : -INFINITY;
    float m = fmaxf(acc0, v1);
    #pragma unroll
    for (int o = 16; o; o >>= 1) m = fmaxf(m, __shfl_xor_sync(0xffffffffu, m, o));
    float s = expf(acc0 - m) + (has1 ? expf(acc1 - m) : 0.f);
    #pragma unroll
    for (int o = 16; o; o >>= 1) s += __shfl_xor_sync(0xffffffffu, s, o);
    float lse = m + logf(s);

    out[(size_t)n * NC + lane] = acc0 - lse;
    if (has1) out[(size_t)n * NC + 32 + lane] = acc1 - lse;
}

// ---------------- launch -----------------------------------------------------
extern "C" void kernel_launch(void* const* d_in, const int* in_sizes, int n_in,
                              void* d_out, int out_size) {
    const float* x   = (const float*)d_in[0];
    const int*   ew  = (const int*)d_in[1];   // edge buffer as 32-bit words
    const float* W1l = (const float*)d_in[2];
    const float* W1r = (const float*)d_in[3];
    const float* b1  = (const float*)d_in[4];
    const float* W2l = (const float*)d_in[5];
    const float* W2r = (const float*)d_in[6];
    const float* b2  = (const float*)d_in[7];
    float*       out = (float*)d_out;

    const int N = in_sizes[0] / F_IN;   // 100000
    const int E = in_sizes[1] / 2;      // 1600000
    const int nb = (N + SCAN_B - 1) / SCAN_B;

    k_detect<<<1, 1024>>>(ew);
    k_zero  <<<(N + 255) / 256, 256>>>(N);
    k_deg   <<<(E + 255) / 256, 256>>>(ew, E, N);
    k_scanA <<<nb, SCAN_B>>>(N);
    k_scanB <<<1, 128>>>(nb);
    k_scanC <<<(N + 255) / 256, 256>>>(N);
    k_fill  <<<(E + 255) / 256, 256>>>(ew, E, N);
    k_gemm1 <<<(N + 63) / 64, 512>>>(x, W1l, W1r, N);
    k_l1    <<<(N + 7) / 8, 256>>>(b1, N);
    k_out   <<<(N + 7) / 8, 256>>>(W2l, W2r, b2, out, N);
}

// round 5
// speedup vs baseline: 1.0014x; 1.0014x over previous
#include <cuda_runtime.h>
#include <math.h>
#include <stdint.h>

#define NN 100000
#define EE 1600000
#define F_IN 256
#define DIM  32
#define NC   40
#define CSR_CAP (EE + 3 * NN)    // padded CSR capacity

// ---------------- scratch (device globals) -----------------------------------
__device__ __align__(256) float g_y[(NN + 1) * DIM];
__device__ __align__(256) float g_r[(NN + 1) * DIM];
__device__ __align__(256) float g_h[(NN + 1) * DIM];
__device__ __align__(256) float g_invdeg[NN];
__device__ __align__(256) int   g_degi[NN];
__device__ __align__(256) int   g_rowptr[NN];
__device__ __align__(256) int   g_cur[NN];
__device__ __align__(256) int   g_csr[CSR_CAP];
__device__ __align__(256) int   g_blksum[128];
__device__ int g_shift;   // 1 if edge_index is int64, 0 if int32

// ---------------- packed f32x2 helpers ----------------------------------------
__device__ __forceinline__ unsigned long long pack2(float a, float b) {
    unsigned long long d;
    asm("mov.b64 %0, {%1,%2};" : "=l"(d) : "f"(a), "f"(b));
    return d;
}
__device__ __forceinline__ void unpack2(unsigned long long d, float& a, float& b) {
    asm("mov.b64 {%0,%1}, %2;" : "=f"(a), "=f"(b) : "l"(d));
}
__device__ __forceinline__ void fma2(unsigned long long& d,
                                     unsigned long long a, unsigned long long b) {
    asm("fma.rn.f32x2 %0, %1, %2, %0;" : "+l"(d) : "l"(a), "l"(b));
}
__device__ __forceinline__ int edge_get(const int* __restrict__ w, int E,
                                        int which, int e, int shift, int N) {
    int v = w[(size_t)((size_t)which * E + e) << shift];
    return min(max(v, 0), N - 1);
}

// ---------------- k_zero: csr pad-init, deg=0, pad rows, dtype detect --------
__global__ void k_zero(const int* __restrict__ w, int N, int padn) {
    int i = blockIdx.x * blockDim.x + threadIdx.x;
    if (i < padn) g_csr[i] = N;
    if (i < N)    g_degi[i] = 0;
    if (i < DIM) { g_y[(size_t)N * DIM + i] = 0.f; g_h[(size_t)N * DIM + i] = 0.f; }
    if (blockIdx.x == 0) {
        __shared__ int any_nz;
        if (threadIdx.x == 0) any_nz = 0;
        __syncthreads();
        int nz = 0;
        #pragma unroll
        for (int j = 0; j < 8; ++j)
            nz |= w[2 * (threadIdx.x * 8 + j) + 1];
        if (nz) atomicOr(&any_nz, 1);
        __syncthreads();
        if (threadIdx.x == 0) g_shift = any_nz ? 0 : 1;
    }
}

__global__ void k_deg(const int* __restrict__ w, int E, int N) {
    int i = blockIdx.x * blockDim.x + threadIdx.x;
    if (i >= E) return;
    atomicAdd(&g_degi[edge_get(w, E, 1, i, g_shift, N)], 1);
}

// ---------------- scans (padded degrees) ---------------------------------------
__global__ void __launch_bounds__(1024) k_scanA(int N) {
    __shared__ int wsum[32];
    int t = threadIdx.x, i = blockIdx.x * 1024 + t;
    int lane = t & 31, w = t >> 5;
    int deg = (i < N) ? g_degi[i] : 0;
    int v = (deg + 3) & ~3;                     // padded degree
    int inc = v;
    #pragma unroll
    for (int o = 1; o < 32; o <<= 1) {
        int u = __shfl_up_sync(0xffffffffu, inc, o);
        if (lane >= o) inc += u;
    }
    if (lane == 31) wsum[w] = inc;
    __syncthreads();
    if (w == 0) {
        int s = wsum[lane], si = s;
        #pragma unroll
        for (int o = 1; o < 32; o <<= 1) {
            int u = __shfl_up_sync(0xffffffffu, si, o);
            if (lane >= o) si += u;
        }
        wsum[lane] = si - s;
        if (lane == 31) g_blksum[blockIdx.x] = si;
    }
    __syncthreads();
    if (i < N) g_rowptr[i] = inc - v + wsum[w];
}

__global__ void __launch_bounds__(128) k_scanB(int nb) {
    __shared__ int sm[128];
    int t = threadIdx.x;
    int v = (t < nb) ? g_blksum[t] : 0;
    sm[t] = v;
    __syncthreads();
    #pragma unroll
    for (int o = 1; o < 128; o <<= 1) {
        int add = (t >= o) ? sm[t - o] : 0;
        __syncthreads();
        sm[t] += add;
        __syncthreads();
    }
    if (t < nb) g_blksum[t] = sm[t] - v;
}

__global__ void k_scanC(int N) {
    int i = blockIdx.x * blockDim.x + threadIdx.x;
    if (i >= N) return;
    int rp = g_rowptr[i] + g_blksum[i >> 10];
    g_rowptr[i] = rp;
    g_cur[i] = rp;
    g_invdeg[i] = 1.0f / fmaxf((float)g_degi[i], 1.0f);
}

__global__ void k_fill(const int* __restrict__ w, int E, int N) {
    int e = blockIdx.x * blockDim.x + threadIdx.x;
    if (e >= E) return;
    int shift = g_shift;
    int s = edge_get(w, E, 0, e, shift, N);
    int d = edge_get(w, E, 1, e, shift, N);
    int pos = atomicAdd(&g_cur[d], 1);
    g_csr[min(pos, CSR_CAP - 1)] = s;
}

// ---------------- GEMM1: y = x@W1l, r = x@W1r ---------------------------------
// f32x2 lanes carry (even-k, odd-k) partial sums: x pairs come free from
// float4 loads; weights staged pre-packed as u64 (W[2k][c], W[2k+1][c]).
// Inner step: 2 x LDS.64 + 8 x FFMA2, zero ALU movs.
__global__ void __launch_bounds__(512) k_gemm1(const float* __restrict__ x,
                                               const float* __restrict__ W1l,
                                               const float* __restrict__ W1r,
                                               int N) {
    __shared__ unsigned long long sWl[64 * DIM];   // 16 KB (64 k-pairs per half)
    __shared__ unsigned long long sWr[64 * DIM];   // 16 KB
    const int warp = threadIdx.x >> 5;
    const int lane = threadIdx.x & 31;
    const int row0 = blockIdx.x * 64 + warp * 4;

    const int r0 = min(row0 + 0, N - 1);
    const int r1 = min(row0 + 1, N - 1);
    const int r2 = min(row0 + 2, N - 1);
    const int r3 = min(row0 + 3, N - 1);

    unsigned long long al0 = 0, al1 = 0, al2 = 0, al3 = 0;   // y accum (even,odd)
    unsigned long long ar0 = 0, ar1 = 0, ar2 = 0, ar3 = 0;   // r accum (even,odd)

    for (int half = 0; half < 2; ++half) {
        const int kbase = half * 128;
        if (half) __syncthreads();
        for (int i = threadIdx.x; i < 64 * DIM; i += 512) {
            int kp = i >> 5, c = i & 31;
            int k = kbase + 2 * kp;
            sWl[i] = pack2(W1l[k * DIM + c], W1l[(k + 1) * DIM + c]);
            sWr[i] = pack2(W1r[k * DIM + c], W1r[(k + 1) * DIM + c]);
        }
        __syncthreads();

        const float4* x0 = (const float4*)(x + (size_t)r0 * F_IN + kbase);
        const float4* x1 = (const float4*)(x + (size_t)r1 * F_IN + kbase);
        const float4* x2 = (const float4*)(x + (size_t)r2 * F_IN + kbase);
        const float4* x3 = (const float4*)(x + (size_t)r3 * F_IN + kbase);

        #pragma unroll 4
        for (int q = 0; q < 32; ++q) {            // 32 float4 per row per half
            float4 v0 = x0[q], v1 = x1[q], v2 = x2[q], v3 = x3[q];
            const unsigned long long* pv0 = (const unsigned long long*)&v0;
            const unsigned long long* pv1 = (const unsigned long long*)&v1;
            const unsigned long long* pv2 = (const unsigned long long*)&v2;
            const unsigned long long* pv3 = (const unsigned long long*)&v3;
            #pragma unroll
            for (int j = 0; j < 2; ++j) {         // two k-pairs per float4
                unsigned long long wl = sWl[(q * 2 + j) * DIM + lane];
                unsigned long long wr = sWr[(q * 2 + j) * DIM + lane];
                fma2(al0, pv0[j], wl); fma2(ar0, pv0[j], wr);
                fma2(al1, pv1[j], wl); fma2(ar1, pv1[j], wr);
                fma2(al2, pv2[j], wl); fma2(ar2, pv2[j], wr);
                fma2(al3, pv3[j], wl); fma2(ar3, pv3[j], wr);
            }
        }
    }

    float e, o;
    if (row0 + 0 < N) {
        unpack2(al0, e, o); g_y[(size_t)r0 * DIM + lane] = e + o;
        unpack2(ar0, e, o); g_r[(size_t)r0 * DIM + lane] = e + o;
    }
    if (row0 + 1 < N) {
        unpack2(al1, e, o); g_y[(size_t)r1 * DIM + lane] = e + o;
        unpack2(ar1, e, o); g_r[(size_t)r1 * DIM + lane] = e + o;
    }
    if (row0 + 2 < N) {
        unpack2(al2, e, o); g_y[(size_t)r2 * DIM + lane] = e + o;
        unpack2(ar2, e, o); g_r[(size_t)r2 * DIM + lane] = e + o;
    }
    if (row0 + 3 < N) {
        unpack2(al3, e, o); g_y[(size_t)r3 * DIM + lane] = e + o;
        unpack2(ar3, e, o); g_r[(size_t)r3 * DIM + lane] = e + o;
    }
}

// ---------------- layer 1: gather(y) -> h = relu(agg*invd + r + b1) -----------
__global__ void __launch_bounds__(256) k_l1(const float* __restrict__ b1, int N) {
    int warp = threadIdx.x >> 5;
    int lane = threadIdx.x & 31;
    int n = blockIdx.x * 8 + warp;
    if (n >= N) return;

    int start = g_rowptr[n];
    int dn    = g_degi[n];
    int dnp   = (dn + 3) & ~3;                  // padded slots index zero-row N
    float acc0 = 0.f, acc1 = 0.f;
    for (int j0 = 0; j0 < dnp; j0 += 32) {
        int m = min(32, dnp - j0);              // multiple of 4
        int idx = (lane < m) ? g_csr[start + j0 + lane] : N;
        for (int k = 0; k < m; k += 4) {
            int s0 = __shfl_sync(0xffffffffu, idx, k);
            int s1 = __shfl_sync(0xffffffffu, idx, k + 1);
            int s2 = __shfl_sync(0xffffffffu, idx, k + 2);
            int s3 = __shfl_sync(0xffffffffu, idx, k + 3);
            float v0 = g_y[(size_t)s0 * DIM + lane];
            float v1 = g_y[(size_t)s1 * DIM + lane];
            float v2 = g_y[(size_t)s2 * DIM + lane];
            float v3 = g_y[(size_t)s3 * DIM + lane];
            acc0 += v0 + v1;
            acc1 += v2 + v3;
        }
    }
    float v = (acc0 + acc1) * g_invdeg[n] + g_r[(size_t)n * DIM + lane] + b1[lane];
    g_h[(size_t)n * DIM + lane] = fmaxf(v, 0.f);
}

// ---------------- layer 2 + log_softmax (fused gather + packed FFMA2) ---------
__global__ void __launch_bounds__(256) k_out(const float* __restrict__ W2l,
                                             const float* __restrict__ W2r,
                                             const float* __restrict__ b2,
                                             float* __restrict__ out, int N) {
    __shared__ unsigned long long sW2[DIM * 64];   // (Wl, Wr) pairs, cols padded
    for (int i = threadIdx.x; i < DIM * 64; i += 256) {
        int k = i >> 6, c = i & 63;
        float wl = (c < NC) ? W2l[k * NC + c] : 0.f;
        float wr = (c < NC) ? W2r[k * NC + c] : 0.f;
        sW2[i] = pack2(wl, wr);
    }
    __syncthreads();

    int warp = threadIdx.x >> 5;
    int lane = threadIdx.x & 31;
    int n = blockIdx.x * 8 + warp;
    if (n >= N) return;

    int start = g_rowptr[n];
    int dn    = g_degi[n];
    int dnp   = (dn + 3) & ~3;
    float acc0g = 0.f, acc1g = 0.f;
    for (int j0 = 0; j0 < dnp; j0 += 32) {
        int m = min(32, dnp - j0);
        int idx = (lane < m) ? g_csr[start + j0 + lane] : N;
        for (int k = 0; k < m; k += 4) {
            int s0 = __shfl_sync(0xffffffffu, idx, k);
            int s1 = __shfl_sync(0xffffffffu, idx, k + 1);
            int s2 = __shfl_sync(0xffffffffu, idx, k + 2);
            int s3 = __shfl_sync(0xffffffffu, idx, k + 3);
            float v0 = g_h[(size_t)s0 * DIM + lane];
            float v1 = g_h[(size_t)s1 * DIM + lane];
            float v2 = g_h[(size_t)s2 * DIM + lane];
            float v3 = g_h[(size_t)s3 * DIM + lane];
            acc0g += v0 + v1;
            acc1g += v2 + v3;
        }
    }
    float a_l = (acc0g + acc1g) * g_invdeg[n];
    float h_l = g_h[(size_t)n * DIM + lane];

    unsigned long long p0 = 0ull, p1 = 0ull;
    #pragma unroll
    for (int k = 0; k < DIM; ++k) {
        float ak = __shfl_sync(0xffffffffu, a_l, k);
        float hk = __shfl_sync(0xffffffffu, h_l, k);
        unsigned long long ap = pack2(ak, hk);
        fma2(p0, ap, sW2[k * 64 + lane]);
        fma2(p1, ap, sW2[k * 64 + 32 + lane]);
    }
    float s0l, s0h, s1l, s1h;
    unpack2(p0, s0l, s0h);
    unpack2(p1, s1l, s1h);

    bool has1 = (lane < NC - 32);
    float acc0 = b2[lane] + s0l + s0h;
    float acc1 = (has1 ? b2[32 + lane] : 0.f) + s1l + s1h;

    float v1 = has1 ? acc1 : -INFINITY;
    float m = fmaxf(acc0, v1);
    #pragma unroll
    for (int o = 16; o; o >>= 1) m = fmaxf(m, __shfl_xor_sync(0xffffffffu, m, o));
    float s = expf(acc0 - m) + (has1 ? expf(acc1 - m) : 0.f);
    #pragma unroll
    for (int o = 16; o; o >>= 1) s += __shfl_xor_sync(0xffffffffu, s, o);
    float lse = m + logf(s);

    out[(size_t)n * NC + lane] = acc0 - lse;
    if (has1) out[(size_t)n * NC + 32 + lane] = acc1 - lse;
}

// ---------------- launch --------------------------------------------------------
extern "C" void kernel_launch(void* const* d_in, const int* in_sizes, int n_in,
                              void* d_out, int out_size) {
    const float* x   = (const float*)d_in[0];
    const int*   ew  = (const int*)d_in[1];
    const float* W1l = (const float*)d_in[2];
    const float* W1r = (const float*)d_in[3];
    const float* b1  = (const float*)d_in[4];
    const float* W2l = (const float*)d_in[5];
    const float* W2r = (const float*)d_in[6];
    const float* b2  = (const float*)d_in[7];
    float*       out = (float*)d_out;

    const int N = in_sizes[0] / F_IN;   // 100000
    const int E = in_sizes[1] / 2;      // 1600000
    const int nb = (N + 1023) / 1024;
    const int padn = E + 3 * N;

    k_zero <<<(padn + 255) / 256, 256>>>(ew, N, padn);
    k_deg  <<<(E + 255) / 256,    256>>>(ew, E, N);
    k_scanA<<<nb, 1024>>>(N);
    k_scanB<<<1, 128>>>(nb);
    k_scanC<<<(N + 255) / 256, 256>>>(N);
    k_gemm1<<<(N + 63) / 64, 512>>>(x, W1l, W1r, N);   // 6th launch: ncu window
    k_fill <<<(E + 255) / 256, 256>>>(ew, E, N);
    k_l1   <<<(N + 7) / 8, 256>>>(b1, N);
    k_out  <<<(N + 7) / 8, 256>>>(W2l, W2r, b2, out, N);
}

// round 6
// speedup vs baseline: 1.0223x; 1.0209x over previous
#include <cuda_runtime.h>
#include <math.h>
#include <stdint.h>

#define NN 100000
#define EE 1600000
#define F_IN 256
#define DIM  32
#define NC   40

// ---------------- scratch (device globals) -----------------------------------
__device__ __align__(256) float g_y[(NN + 1) * DIM];
__device__ __align__(256) float g_r[(NN + 1) * DIM];
__device__ __align__(256) float g_h[(NN + 1) * DIM];
__device__ __align__(256) float g_invdeg[NN];
__device__ __align__(256) int   g_degi[NN];
__device__ __align__(256) int   g_rowptr[NN];
__device__ __align__(256) int   g_cur[NN];
__device__ __align__(256) int   g_csr[EE];
__device__ __align__(256) int   g_blksum[128];
__device__ int g_shift;   // 1 if edge_index is int64, 0 if int32

// ---------------- packed f32x2 helpers ----------------------------------------
__device__ __forceinline__ unsigned long long pack2(float a, float b) {
    unsigned long long d;
    asm("mov.b64 %0, {%1,%2};" : "=l"(d) : "f"(a), "f"(b));
    return d;
}
__device__ __forceinline__ void unpack2(unsigned long long d, float& a, float& b) {
    asm("mov.b64 {%0,%1}, %2;" : "=f"(a), "=f"(b) : "l"(d));
}
__device__ __forceinline__ void fma2(unsigned long long& d,
                                     unsigned long long a, unsigned long long b) {
    asm("fma.rn.f32x2 %0, %1, %2, %0;" : "+l"(d) : "l"(a), "l"(b));
}
__device__ __forceinline__ int clampN(int v, int N) {
    return min(max(v, 0), N - 1);
}
__device__ __forceinline__ int edge_get(const int* __restrict__ w, int E,
                                        int which, int e, int shift, int N) {
    int v = w[(size_t)((size_t)which * E + e) << shift];
    return clampN(v, N);
}

// ---------------- k_zero: deg=0, zero-row init, dtype detect ------------------
__global__ void k_zero(const int* __restrict__ w, int N) {
    int i = blockIdx.x * blockDim.x + threadIdx.x;
    if (i < N) g_degi[i] = 0;
    if (i < DIM) { g_y[(size_t)N * DIM + i] = 0.f; g_h[(size_t)N * DIM + i] = 0.f; }
    if (blockIdx.x == 0) {
        __shared__ int any_nz;
        if (threadIdx.x == 0) any_nz = 0;
        __syncthreads();
        int nz = 0;
        #pragma unroll
        for (int j = 0; j < 8; ++j)
            nz |= w[2 * (threadIdx.x * 8 + j) + 1];
        if (nz && threadIdx.x < 256) atomicOr(&any_nz, 1);
        __syncthreads();
        if (threadIdx.x == 0) g_shift = any_nz ? 0 : 1;
    }
}

// ---------------- k_deg: 4 edges/thread, vectorized dst reads -----------------
__global__ void k_deg(const int* __restrict__ w, int E, int N) {
    int e = (blockIdx.x * blockDim.x + threadIdx.x) * 4;
    if (e >= E) return;
    int shift = g_shift;
    if (e + 4 <= E) {
        int d0, d1, d2, d3;
        if (shift) {   // int64: low words at even offsets
            const int4* p = (const int4*)(w + (((size_t)E + e) << 1));
            int4 a = p[0], b = p[1];
            d0 = a.x; d1 = a.z; d2 = b.x; d3 = b.z;
        } else {
            int4 a = *(const int4*)(w + (size_t)E + e);
            d0 = a.x; d1 = a.y; d2 = a.z; d3 = a.w;
        }
        atomicAdd(&g_degi[clampN(d0, N)], 1);
        atomicAdd(&g_degi[clampN(d1, N)], 1);
        atomicAdd(&g_degi[clampN(d2, N)], 1);
        atomicAdd(&g_degi[clampN(d3, N)], 1);
    } else {
        for (int k = e; k < E; ++k)
            atomicAdd(&g_degi[edge_get(w, E, 1, k, shift, N)], 1);
    }
}

// ---------------- scanA: per-1024-block exclusive scan of degrees -------------
__global__ void __launch_bounds__(1024) k_scanA(int N) {
    __shared__ int wsum[32];
    int t = threadIdx.x, i = blockIdx.x * 1024 + t;
    int lane = t & 31, w = t >> 5;
    int v = (i < N) ? g_degi[i] : 0;
    int inc = v;
    #pragma unroll
    for (int o = 1; o < 32; o <<= 1) {
        int u = __shfl_up_sync(0xffffffffu, inc, o);
        if (lane >= o) inc += u;
    }
    if (lane == 31) wsum[w] = inc;
    __syncthreads();
    if (w == 0) {
        int s = wsum[lane], si = s;
        #pragma unroll
        for (int o = 1; o < 32; o <<= 1) {
            int u = __shfl_up_sync(0xffffffffu, si, o);
            if (lane >= o) si += u;
        }
        wsum[lane] = si - s;
        if (lane == 31) g_blksum[blockIdx.x] = si;
    }
    __syncthreads();
    if (i < N) g_rowptr[i] = inc - v + wsum[w];
}

// ---------------- scanC (absorbs scanB): per-block local blksum prefix --------
__global__ void __launch_bounds__(256) k_scanC(int N, int nb) {
    __shared__ int sp0, sb0;
    int i0 = blockIdx.x * 256;
    int b0 = i0 >> 10;
    if (threadIdx.x < 32) {
        int lane = threadIdx.x;
        int s = 0;
        for (int j = lane; j < b0; j += 32) s += g_blksum[j];
        #pragma unroll
        for (int o = 16; o; o >>= 1) s += __shfl_xor_sync(0xffffffffu, s, o);
        if (lane == 0) { sp0 = s; sb0 = (b0 + 1 < nb) ? g_blksum[b0] : 0; }
    }
    __syncthreads();
    int i = i0 + threadIdx.x;
    if (i >= N) return;
    int off = ((i >> 10) == b0) ? sp0 : sp0 + sb0;
    int rp = g_rowptr[i] + off;
    g_rowptr[i] = rp;
    g_cur[i] = rp;
    g_invdeg[i] = 1.0f / fmaxf((float)g_degi[i], 1.0f);
}

// ---------------- k_fill: 2 edges/thread, vectorized ---------------------------
__global__ void k_fill(const int* __restrict__ w, int E, int N) {
    int e = (blockIdx.x * blockDim.x + threadIdx.x) * 2;
    if (e >= E) return;
    int shift = g_shift;
    if (e + 2 <= E) {
        int s0, s1, d0, d1;
        if (shift) {
            int4 a = *(const int4*)(w + ((size_t)e << 1));
            int4 b = *(const int4*)(w + (((size_t)E + e) << 1));
            s0 = a.x; s1 = a.z; d0 = b.x; d1 = b.z;
        } else {
            int2 a = *(const int2*)(w + (size_t)e);
            int2 b = *(const int2*)(w + (size_t)E + e);
            s0 = a.x; s1 = a.y; d0 = b.x; d1 = b.y;
        }
        s0 = clampN(s0, N); s1 = clampN(s1, N);
        d0 = clampN(d0, N); d1 = clampN(d1, N);
        int p0 = atomicAdd(&g_cur[d0], 1);
        g_csr[min(p0, EE - 1)] = s0;
        int p1 = atomicAdd(&g_cur[d1], 1);
        g_csr[min(p1, EE - 1)] = s1;
    } else {
        int s = edge_get(w, E, 0, e, shift, N);
        int d = edge_get(w, E, 1, e, shift, N);
        int pos = atomicAdd(&g_cur[d], 1);
        g_csr[min(pos, EE - 1)] = s;
    }
}

// ---------------- GEMM1: y = x@W1l, r = x@W1r (packed even/odd-k FFMA2) -------
__global__ void __launch_bounds__(512) k_gemm1(const float* __restrict__ x,
                                               const float* __restrict__ W1l,
                                               const float* __restrict__ W1r,
                                               int N) {
    __shared__ unsigned long long sWl[64 * DIM];
    __shared__ unsigned long long sWr[64 * DIM];
    const int warp = threadIdx.x >> 5;
    const int lane = threadIdx.x & 31;
    const int row0 = blockIdx.x * 64 + warp * 4;

    const int r0 = min(row0 + 0, N - 1);
    const int r1 = min(row0 + 1, N - 1);
    const int r2 = min(row0 + 2, N - 1);
    const int r3 = min(row0 + 3, N - 1);

    unsigned long long al0 = 0, al1 = 0, al2 = 0, al3 = 0;
    unsigned long long ar0 = 0, ar1 = 0, ar2 = 0, ar3 = 0;

    for (int half = 0; half < 2; ++half) {
        const int kbase = half * 128;
        if (half) __syncthreads();
        for (int i = threadIdx.x; i < 64 * DIM; i += 512) {
            int kp = i >> 5, c = i & 31;
            int k = kbase + 2 * kp;
            sWl[i] = pack2(W1l[k * DIM + c], W1l[(k + 1) * DIM + c]);
            sWr[i] = pack2(W1r[k * DIM + c], W1r[(k + 1) * DIM + c]);
        }
        __syncthreads();

        const float4* x0 = (const float4*)(x + (size_t)r0 * F_IN + kbase);
        const float4* x1 = (const float4*)(x + (size_t)r1 * F_IN + kbase);
        const float4* x2 = (const float4*)(x + (size_t)r2 * F_IN + kbase);
        const float4* x3 = (const float4*)(x + (size_t)r3 * F_IN + kbase);

        #pragma unroll 4
        for (int q = 0; q < 32; ++q) {
            float4 v0 = x0[q], v1 = x1[q], v2 = x2[q], v3 = x3[q];
            const unsigned long long* pv0 = (const unsigned long long*)&v0;
            const unsigned long long* pv1 = (const unsigned long long*)&v1;
            const unsigned long long* pv2 = (const unsigned long long*)&v2;
            const unsigned long long* pv3 = (const unsigned long long*)&v3;
            #pragma unroll
            for (int j = 0; j < 2; ++j) {
                unsigned long long wl = sWl[(q * 2 + j) * DIM + lane];
                unsigned long long wr = sWr[(q * 2 + j) * DIM + lane];
                fma2(al0, pv0[j], wl); fma2(ar0, pv0[j], wr);
                fma2(al1, pv1[j], wl); fma2(ar1, pv1[j], wr);
                fma2(al2, pv2[j], wl); fma2(ar2, pv2[j], wr);
                fma2(al3, pv3[j], wl); fma2(ar3, pv3[j], wr);
            }
        }
    }

    float e, o;
    if (row0 + 0 < N) {
        unpack2(al0, e, o); g_y[(size_t)r0 * DIM + lane] = e + o;
        unpack2(ar0, e, o); g_r[(size_t)r0 * DIM + lane] = e + o;
    }
    if (row0 + 1 < N) {
        unpack2(al1, e, o); g_y[(size_t)r1 * DIM + lane] = e + o;
        unpack2(ar1, e, o); g_r[(size_t)r1 * DIM + lane] = e + o;
    }
    if (row0 + 2 < N) {
        unpack2(al2, e, o); g_y[(size_t)r2 * DIM + lane] = e + o;
        unpack2(ar2, e, o); g_r[(size_t)r2 * DIM + lane] = e + o;
    }
    if (row0 + 3 < N) {
        unpack2(al3, e, o); g_y[(size_t)r3 * DIM + lane] = e + o;
        unpack2(ar3, e, o); g_r[(size_t)r3 * DIM + lane] = e + o;
    }
}

// ---------------- layer 1: gather(y) -> h = relu(agg*invd + r + b1) -----------
__global__ void __launch_bounds__(256) k_l1(const float* __restrict__ b1, int N) {
    int warp = threadIdx.x >> 5;
    int lane = threadIdx.x & 31;
    int n = blockIdx.x * 8 + warp;
    if (n >= N) return;

    int start = g_rowptr[n];
    int dn    = g_degi[n];
    int dnp   = (dn + 3) & ~3;
    float acc0 = 0.f, acc1 = 0.f;
    for (int j0 = 0; j0 < dnp; j0 += 32) {
        int m = min(32, dnp - j0);              // multiple of 4
        int idx = (j0 + lane < dn) ? g_csr[start + j0 + lane] : N;
        for (int k = 0; k < m; k += 4) {
            int s0 = __shfl_sync(0xffffffffu, idx, k);
            int s1 = __shfl_sync(0xffffffffu, idx, k + 1);
            int s2 = __shfl_sync(0xffffffffu, idx, k + 2);
            int s3 = __shfl_sync(0xffffffffu, idx, k + 3);
            float v0 = g_y[(size_t)s0 * DIM + lane];
            float v1 = g_y[(size_t)s1 * DIM + lane];
            float v2 = g_y[(size_t)s2 * DIM + lane];
            float v3 = g_y[(size_t)s3 * DIM + lane];
            acc0 += v0 + v1;
            acc1 += v2 + v3;
        }
    }
    float v = (acc0 + acc1) * g_invdeg[n] + g_r[(size_t)n * DIM + lane] + b1[lane];
    g_h[(size_t)n * DIM + lane] = fmaxf(v, 0.f);
}

// ---------------- layer 2 + log_softmax ---------------------------------------
__global__ void __launch_bounds__(256) k_out(const float* __restrict__ W2l,
                                             const float* __restrict__ W2r,
                                             const float* __restrict__ b2,
                                             float* __restrict__ out, int N) {
    __shared__ unsigned long long sW2[DIM * 64];
    for (int i = threadIdx.x; i < DIM * 64; i += 256) {
        int k = i >> 6, c = i & 63;
        float wl = (c < NC) ? W2l[k * NC + c] : 0.f;
        float wr = (c < NC) ? W2r[k * NC + c] : 0.f;
        sW2[i] = pack2(wl, wr);
    }
    __syncthreads();

    int warp = threadIdx.x >> 5;
    int lane = threadIdx.x & 31;
    int n = blockIdx.x * 8 + warp;
    if (n >= N) return;

    int start = g_rowptr[n];
    int dn    = g_degi[n];
    int dnp   = (dn + 3) & ~3;
    float acc0g = 0.f, acc1g = 0.f;
    for (int j0 = 0; j0 < dnp; j0 += 32) {
        int m = min(32, dnp - j0);
        int idx = (j0 + lane < dn) ? g_csr[start + j0 + lane] : N;
        for (int k = 0; k < m; k += 4) {
            int s0 = __shfl_sync(0xffffffffu, idx, k);
            int s1 = __shfl_sync(0xffffffffu, idx, k + 1);
            int s2 = __shfl_sync(0xffffffffu, idx, k + 2);
            int s3 = __shfl_sync(0xffffffffu, idx, k + 3);
            float v0 = g_h[(size_t)s0 * DIM + lane];
            float v1 = g_h[(size_t)s1 * DIM + lane];
            float v2 = g_h[(size_t)s2 * DIM + lane];
            float v3 = g_h[(size_t)s3 * DIM + lane];
            acc0g += v0 + v1;
            acc1g += v2 + v3;
        }
    }
    float a_l = (acc0g + acc1g) * g_invdeg[n];
    float h_l = g_h[(size_t)n * DIM + lane];

    unsigned long long p0 = 0ull, p1 = 0ull;
    #pragma unroll
    for (int k = 0; k < DIM; ++k) {
        float ak = __shfl_sync(0xffffffffu, a_l, k);
        float hk = __shfl_sync(0xffffffffu, h_l, k);
        unsigned long long ap = pack2(ak, hk);
        fma2(p0, ap, sW2[k * 64 + lane]);
        fma2(p1, ap, sW2[k * 64 + 32 + lane]);
    }
    float s0l, s0h, s1l, s1h;
    unpack2(p0, s0l, s0h);
    unpack2(p1, s1l, s1h);

    bool has1 = (lane < NC - 32);
    float acc0 = b2[lane] + s0l + s0h;
    float acc1 = (has1 ? b2[32 + lane] : 0.f) + s1l + s1h;

    float v1 = has1 ? acc1 : -INFINITY;
    float m = fmaxf(acc0, v1);
    #pragma unroll
    for (int o = 16; o; o >>= 1) m = fmaxf(m, __shfl_xor_sync(0xffffffffu, m, o));
    float s = expf(acc0 - m) + (has1 ? expf(acc1 - m) : 0.f);
    #pragma unroll
    for (int o = 16; o; o >>= 1) s += __shfl_xor_sync(0xffffffffu, s, o);
    float lse = m + logf(s);

    out[(size_t)n * NC + lane] = acc0 - lse;
    if (has1) out[(size_t)n * NC + 32 + lane] = acc1 - lse;
}

// ---------------- launch --------------------------------------------------------
extern "C" void kernel_launch(void* const* d_in, const int* in_sizes, int n_in,
                              void* d_out, int out_size) {
    const float* x   = (const float*)d_in[0];
    const int*   ew  = (const int*)d_in[1];
    const float* W1l = (const float*)d_in[2];
    const float* W1r = (const float*)d_in[3];
    const float* b1  = (const float*)d_in[4];
    const float* W2l = (const float*)d_in[5];
    const float* W2r = (const float*)d_in[6];
    const float* b2  = (const float*)d_in[7];
    float*       out = (float*)d_out;

    const int N = in_sizes[0] / F_IN;   // 100000
    const int E = in_sizes[1] / 2;      // 1600000
    const int nb = (N + 1023) / 1024;

    k_zero <<<(N + 255) / 256, 256>>>(ew, N);
    k_deg  <<<(E / 4 + 255) / 256, 256>>>(ew, E, N);
    k_scanA<<<nb, 1024>>>(N);
    k_gemm1<<<(N + 63) / 64, 512>>>(x, W1l, W1r, N);   // 4th launch: ncu window
    k_scanC<<<(N + 255) / 256, 256>>>(N, nb);
    k_fill <<<(E / 2 + 255) / 256, 256>>>(ew, E, N);
    k_l1   <<<(N + 7) / 8, 256>>>(b1, N);
    k_out  <<<(N + 7) / 8, 256>>>(W2l, W2r, b2, out, N);
}

// round 7
// speedup vs baseline: 1.3016x; 1.2732x over previous
#include <cuda_runtime.h>
#include <math.h>
#include <stdint.h>

#define NN 100000
#define EE 1600000
#define F_IN 256
#define DIM  32
#define NC   40

// ---------------- scratch (device globals) -----------------------------------
__device__ __align__(256) float g_y[(NN + 1) * DIM];
__device__ __align__(256) float g_r[(NN + 1) * DIM];
__device__ __align__(256) float g_h[(NN + 1) * DIM];
__device__ __align__(256) float g_invdeg[NN];
__device__ __align__(256) int   g_degi[NN];
__device__ __align__(256) int   g_rowptr[NN];
__device__ __align__(256) int   g_cur[NN];
__device__ __align__(256) int   g_csr[EE];
__device__ __align__(256) int   g_blksum[128];
__device__ int g_shift;   // 1 if edge_index is int64, 0 if int32

// ---------------- packed f32x2 helpers ----------------------------------------
__device__ __forceinline__ unsigned long long pack2(float a, float b) {
    unsigned long long d;
    asm("mov.b64 %0, {%1,%2};" : "=l"(d) : "f"(a), "f"(b));
    return d;
}
__device__ __forceinline__ void unpack2(unsigned long long d, float& a, float& b) {
    asm("mov.b64 {%0,%1}, %2;" : "=f"(a), "=f"(b) : "l"(d));
}
__device__ __forceinline__ void fma2(unsigned long long& d,
                                     unsigned long long a, unsigned long long b) {
    asm("fma.rn.f32x2 %0, %1, %2, %0;" : "+l"(d) : "l"(a), "l"(b));
}
__device__ __forceinline__ int clampN(int v, int N) {
    return min(max(v, 0), N - 1);
}
__device__ __forceinline__ int edge_get(const int* __restrict__ w, int E,
                                        int which, int e, int shift, int N) {
    int v = w[(size_t)((size_t)which * E + e) << shift];
    return clampN(v, N);
}

// ---------------- k_zero: deg=0, zero-row init, dtype detect ------------------
__global__ void k_zero(const int* __restrict__ w, int N) {
    int i = blockIdx.x * blockDim.x + threadIdx.x;
    if (i < N) g_degi[i] = 0;
    if (i < DIM) { g_y[(size_t)N * DIM + i] = 0.f; g_h[(size_t)N * DIM + i] = 0.f; }
    if (blockIdx.x == 0) {
        __shared__ int any_nz;
        if (threadIdx.x == 0) any_nz = 0;
        __syncthreads();
        int nz = 0;
        #pragma unroll
        for (int j = 0; j < 8; ++j)
            nz |= w[2 * (threadIdx.x * 8 + j) + 1];
        if (nz && threadIdx.x < 256) atomicOr(&any_nz, 1);
        __syncthreads();
        if (threadIdx.x == 0) g_shift = any_nz ? 0 : 1;
    }
}

// ---------------- k_deg: 4 edges/thread, vectorized dst reads -----------------
__global__ void k_deg(const int* __restrict__ w, int E, int N) {
    int e = (blockIdx.x * blockDim.x + threadIdx.x) * 4;
    if (e >= E) return;
    int shift = g_shift;
    if (e + 4 <= E) {
        int d0, d1, d2, d3;
        if (shift) {
            const int4* p = (const int4*)(w + (((size_t)E + e) << 1));
            int4 a = p[0], b = p[1];
            d0 = a.x; d1 = a.z; d2 = b.x; d3 = b.z;
        } else {
            int4 a = *(const int4*)(w + (size_t)E + e);
            d0 = a.x; d1 = a.y; d2 = a.z; d3 = a.w;
        }
        atomicAdd(&g_degi[clampN(d0, N)], 1);
        atomicAdd(&g_degi[clampN(d1, N)], 1);
        atomicAdd(&g_degi[clampN(d2, N)], 1);
        atomicAdd(&g_degi[clampN(d3, N)], 1);
    } else {
        for (int k = e; k < E; ++k)
            atomicAdd(&g_degi[edge_get(w, E, 1, k, shift, N)], 1);
    }
}

// ---------------- scanA ---------------------------------------------------------
__global__ void __launch_bounds__(1024) k_scanA(int N) {
    __shared__ int wsum[32];
    int t = threadIdx.x, i = blockIdx.x * 1024 + t;
    int lane = t & 31, w = t >> 5;
    int v = (i < N) ? g_degi[i] : 0;
    int inc = v;
    #pragma unroll
    for (int o = 1; o < 32; o <<= 1) {
        int u = __shfl_up_sync(0xffffffffu, inc, o);
        if (lane >= o) inc += u;
    }
    if (lane == 31) wsum[w] = inc;
    __syncthreads();
    if (w == 0) {
        int s = wsum[lane], si = s;
        #pragma unroll
        for (int o = 1; o < 32; o <<= 1) {
            int u = __shfl_up_sync(0xffffffffu, si, o);
            if (lane >= o) si += u;
        }
        wsum[lane] = si - s;
        if (lane == 31) g_blksum[blockIdx.x] = si;
    }
    __syncthreads();
    if (i < N) g_rowptr[i] = inc - v + wsum[w];
}

// ---------------- scanC (absorbs scanB) -----------------------------------------
__global__ void __launch_bounds__(256) k_scanC(int N, int nb) {
    __shared__ int sp0, sb0;
    int i0 = blockIdx.x * 256;
    int b0 = i0 >> 10;
    if (threadIdx.x < 32) {
        int lane = threadIdx.x;
        int s = 0;
        for (int j = lane; j < b0; j += 32) s += g_blksum[j];
        #pragma unroll
        for (int o = 16; o; o >>= 1) s += __shfl_xor_sync(0xffffffffu, s, o);
        if (lane == 0) { sp0 = s; sb0 = (b0 + 1 < nb) ? g_blksum[b0] : 0; }
    }
    __syncthreads();
    int i = i0 + threadIdx.x;
    if (i >= N) return;
    int off = ((i >> 10) == b0) ? sp0 : sp0 + sb0;
    int rp = g_rowptr[i] + off;
    g_rowptr[i] = rp;
    g_cur[i] = rp;
    g_invdeg[i] = 1.0f / fmaxf((float)g_degi[i], 1.0f);
}

// ---------------- k_fill: 2 edges/thread, vectorized -----------------------------
__global__ void k_fill(const int* __restrict__ w, int E, int N) {
    int e = (blockIdx.x * blockDim.x + threadIdx.x) * 2;
    if (e >= E) return;
    int shift = g_shift;
    if (e + 2 <= E) {
        int s0, s1, d0, d1;
        if (shift) {
            int4 a = *(const int4*)(w + ((size_t)e << 1));
            int4 b = *(const int4*)(w + (((size_t)E + e) << 1));
            s0 = a.x; s1 = a.z; d0 = b.x; d1 = b.z;
        } else {
            int2 a = *(const int2*)(w + (size_t)e);
            int2 b = *(const int2*)(w + (size_t)E + e);
            s0 = a.x; s1 = a.y; d0 = b.x; d1 = b.y;
        }
        s0 = clampN(s0, N); s1 = clampN(s1, N);
        d0 = clampN(d0, N); d1 = clampN(d1, N);
        int p0 = atomicAdd(&g_cur[d0], 1);
        g_csr[min(p0, EE - 1)] = s0;
        int p1 = atomicAdd(&g_cur[d1], 1);
        g_csr[min(p1, EE - 1)] = s1;
    } else {
        int s = edge_get(w, E, 0, e, shift, N);
        int d = edge_get(w, E, 1, e, shift, N);
        int pos = atomicAdd(&g_cur[d], 1);
        g_csr[min(pos, EE - 1)] = s;
    }
}

// ---------------- GEMM1: y = x@W1l, r = x@W1r ------------------------------------
// 256 threads, 8 warps, 64 rows/CTA (8 rows/warp), K in 4 quarters of 64.
// x staged in smem (coalesced LDG -> LDS.128 broadcast reads, 1 wavefront each).
// Weights packed ulonglong2 = (wl_pair, wr_pair): one LDS.128 per (q,j).
// Inner q-step per warp: 8 bc-LDS.128 (x) + 2 LDS.128 (w) + 32 FFMA2.
__global__ void __launch_bounds__(256) k_gemm1(const float* __restrict__ x,
                                               const float* __restrict__ W1l,
                                               const float* __restrict__ W1r,
                                               int N) {
    __shared__ ulonglong2 sW[16 * 2 * 32];   // [q][j][c] (wl01, wr01)   16 KB
    __shared__ ulonglong2 sX[64 * 16];       // [row][quad]              16 KB
    const int tid  = threadIdx.x;
    const int warp = tid >> 5;
    const int lane = tid & 31;
    const int row0 = blockIdx.x * 64;

    unsigned long long aL[8], aR[8];
    #pragma unroll
    for (int r = 0; r < 8; ++r) { aL[r] = 0ull; aR[r] = 0ull; }

    for (int quarter = 0; quarter < 4; ++quarter) {
        const int kbase = quarter * 64;
        if (quarter) __syncthreads();
        // stage weights: i = [q:4][j:1][c:5]
        #pragma unroll
        for (int it = 0; it < 4; ++it) {
            int i = tid + 256 * it;
            int c = i & 31, j = (i >> 5) & 1, q = i >> 6;
            int k = kbase + q * 4 + j * 2;
            sW[i] = make_ulonglong2(
                pack2(W1l[k * DIM + c], W1l[(k + 1) * DIM + c]),
                pack2(W1r[k * DIM + c], W1r[(k + 1) * DIM + c]));
        }
        // stage x: i = [row:6][quad:4], coalesced float4 loads
        #pragma unroll
        for (int it = 0; it < 4; ++it) {
            int i = tid + 256 * it;
            int quad = i & 15, row = i >> 4;
            int grow = min(row0 + row, N - 1);
            ((float4*)sX)[i] =
                *(const float4*)(x + (size_t)grow * F_IN + kbase + quad * 4);
        }
        __syncthreads();

        const ulonglong2* xrow = &sX[(warp * 8) * 16];
        #pragma unroll 4
        for (int q = 0; q < 16; ++q) {
            ulonglong2 w0 = sW[(q * 2 + 0) * 32 + lane];   // j=0: (wl01, wr01)
            ulonglong2 w1 = sW[(q * 2 + 1) * 32 + lane];   // j=1
            #pragma unroll
            for (int r = 0; r < 8; ++r) {
                ulonglong2 xv = xrow[r * 16 + q];          // broadcast, 16B quad
                fma2(aL[r], xv.x, w0.x);
                fma2(aR[r], xv.x, w0.y);
                fma2(aL[r], xv.y, w1.x);
                fma2(aR[r], xv.y, w1.y);
            }
        }
    }

    #pragma unroll
    for (int r = 0; r < 8; ++r) {
        int row = row0 + warp * 8 + r;
        if (row < N) {
            float e, o;
            unpack2(aL[r], e, o); g_y[(size_t)row * DIM + lane] = e + o;
            unpack2(aR[r], e, o); g_r[(size_t)row * DIM + lane] = e + o;
        }
    }
}

// ---------------- layer 1: gather(y) -> h = relu(agg*invd + r + b1) --------------
__global__ void __launch_bounds__(256) k_l1(const float* __restrict__ b1, int N) {
    int warp = threadIdx.x >> 5;
    int lane = threadIdx.x & 31;
    int n = blockIdx.x * 8 + warp;
    if (n >= N) return;

    int start = g_rowptr[n];
    int dn    = g_degi[n];
    int dnp   = (dn + 3) & ~3;
    float acc0 = 0.f, acc1 = 0.f;
    for (int j0 = 0; j0 < dnp; j0 += 32) {
        int m = min(32, dnp - j0);
        int idx = (j0 + lane < dn) ? g_csr[start + j0 + lane] : N;
        for (int k = 0; k < m; k += 4) {
            int s0 = __shfl_sync(0xffffffffu, idx, k);
            int s1 = __shfl_sync(0xffffffffu, idx, k + 1);
            int s2 = __shfl_sync(0xffffffffu, idx, k + 2);
            int s3 = __shfl_sync(0xffffffffu, idx, k + 3);
            float v0 = g_y[(size_t)s0 * DIM + lane];
            float v1 = g_y[(size_t)s1 * DIM + lane];
            float v2 = g_y[(size_t)s2 * DIM + lane];
            float v3 = g_y[(size_t)s3 * DIM + lane];
            acc0 += v0 + v1;
            acc1 += v2 + v3;
        }
    }
    float v = (acc0 + acc1) * g_invdeg[n] + g_r[(size_t)n * DIM + lane] + b1[lane];
    g_h[(size_t)n * DIM + lane] = fmaxf(v, 0.f);
}

// ---------------- layer 2 + log_softmax -------------------------------------------
__global__ void __launch_bounds__(256) k_out(const float* __restrict__ W2l,
                                             const float* __restrict__ W2r,
                                             const float* __restrict__ b2,
                                             float* __restrict__ out, int N) {
    __shared__ unsigned long long sW2[DIM * 64];
    for (int i = threadIdx.x; i < DIM * 64; i += 256) {
        int k = i >> 6, c = i & 63;
        float wl = (c < NC) ? W2l[k * NC + c] : 0.f;
        float wr = (c < NC) ? W2r[k * NC + c] : 0.f;
        sW2[i] = pack2(wl, wr);
    }
    __syncthreads();

    int warp = threadIdx.x >> 5;
    int lane = threadIdx.x & 31;
    int n = blockIdx.x * 8 + warp;
    if (n >= N) return;

    int start = g_rowptr[n];
    int dn    = g_degi[n];
    int dnp   = (dn + 3) & ~3;
    float acc0g = 0.f, acc1g = 0.f;
    for (int j0 = 0; j0 < dnp; j0 += 32) {
        int m = min(32, dnp - j0);
        int idx = (j0 + lane < dn) ? g_csr[start + j0 + lane] : N;
        for (int k = 0; k < m; k += 4) {
            int s0 = __shfl_sync(0xffffffffu, idx, k);
            int s1 = __shfl_sync(0xffffffffu, idx, k + 1);
            int s2 = __shfl_sync(0xffffffffu, idx, k + 2);
            int s3 = __shfl_sync(0xffffffffu, idx, k + 3);
            float v0 = g_h[(size_t)s0 * DIM + lane];
            float v1 = g_h[(size_t)s1 * DIM + lane];
            float v2 = g_h[(size_t)s2 * DIM + lane];
            float v3 = g_h[(size_t)s3 * DIM + lane];
            acc0g += v0 + v1;
            acc1g += v2 + v3;
        }
    }
    float a_l = (acc0g + acc1g) * g_invdeg[n];
    float h_l = g_h[(size_t)n * DIM + lane];

    unsigned long long p0 = 0ull, p1 = 0ull;
    #pragma unroll
    for (int k = 0; k < DIM; ++k) {
        float ak = __shfl_sync(0xffffffffu, a_l, k);
        float hk = __shfl_sync(0xffffffffu, h_l, k);
        unsigned long long ap = pack2(ak, hk);
        fma2(p0, ap, sW2[k * 64 + lane]);
        fma2(p1, ap, sW2[k * 64 + 32 + lane]);
    }
    float s0l, s0h, s1l, s1h;
    unpack2(p0, s0l, s0h);
    unpack2(p1, s1l, s1h);

    bool has1 = (lane < NC - 32);
    float acc0 = b2[lane] + s0l + s0h;
    float acc1 = (has1 ? b2[32 + lane] : 0.f) + s1l + s1h;

    float v1 = has1 ? acc1 : -INFINITY;
    float m = fmaxf(acc0, v1);
    #pragma unroll
    for (int o = 16; o; o >>= 1) m = fmaxf(m, __shfl_xor_sync(0xffffffffu, m, o));
    float s = expf(acc0 - m) + (has1 ? expf(acc1 - m) : 0.f);
    #pragma unroll
    for (int o = 16; o; o >>= 1) s += __shfl_xor_sync(0xffffffffu, s, o);
    float lse = m + logf(s);

    out[(size_t)n * NC + lane] = acc0 - lse;
    if (has1) out[(size_t)n * NC + 32 + lane] = acc1 - lse;
}

// ---------------- launch -----------------------------------------------------------
extern "C" void kernel_launch(void* const* d_in, const int* in_sizes, int n_in,
                              void* d_out, int out_size) {
    const float* x   = (const float*)d_in[0];
    const int*   ew  = (const int*)d_in[1];
    const float* W1l = (const float*)d_in[2];
    const float* W1r = (const float*)d_in[3];
    const float* b1  = (const float*)d_in[4];
    const float* W2l = (const float*)d_in[5];
    const float* W2r = (const float*)d_in[6];
    const float* b2  = (const float*)d_in[7];
    float*       out = (float*)d_out;

    const int N = in_sizes[0] / F_IN;   // 100000
    const int E = in_sizes[1] / 2;      // 1600000
    const int nb = (N + 1023) / 1024;

    k_zero <<<(N + 255) / 256, 256>>>(ew, N);
    k_deg  <<<(E / 4 + 255) / 256, 256>>>(ew, E, N);
    k_scanA<<<nb, 1024>>>(N);
    k_gemm1<<<(N + 63) / 64, 256>>>(x, W1l, W1r, N);   // 4th launch: ncu window
    k_scanC<<<(N + 255) / 256, 256>>>(N, nb);
    k_fill <<<(E / 2 + 255) / 256, 256>>>(ew, E, N);
    k_l1   <<<(N + 7) / 8, 256>>>(b1, N);
    k_out  <<<(N + 7) / 8, 256>>>(W2l, W2r, b2, out, N);
}